// round 1
// baseline (speedup 1.0000x reference)
#include <cuda_runtime.h>
#include <math.h>

#define NUM_EMBED 8192
#define EMBED_DIM 64
#define BB 8
#define HH 64
#define WW 64
#define N_TOK   (BB*HH*WW)            /* 32768 */
#define N_ELEM  (BB*EMBED_DIM*HH*WW)  /* 2097152 */
#define HW      (HH*WW)               /* 4096 */
#define N_PART  2048

#define TM 128
#define TN 128

// Scratch (device globals; no allocation allowed)
__device__ float g_enT[EMBED_DIM * NUM_EMBED];  // normalized codebook, [c][n]
__device__ int   g_idx[N_TOK];
__device__ int   g_hist[NUM_EMBED];
__device__ float g_partial[N_PART];

// ---------------------------------------------------------------------------
// Kernel 0: zero histogram
// ---------------------------------------------------------------------------
__global__ void vq_zero_hist() {
    int i = blockIdx.x * 256 + threadIdx.x;
    if (i < NUM_EMBED) g_hist[i] = 0;
}

// ---------------------------------------------------------------------------
// Kernel 1: normalize codebook rows, store transposed [c][n]
// one warp per code row
// ---------------------------------------------------------------------------
__global__ void vq_normalize_embed(const float* __restrict__ emb) {
    int wid  = (blockIdx.x * blockDim.x + threadIdx.x) >> 5;
    int lane = threadIdx.x & 31;
    if (wid >= NUM_EMBED) return;
    const float* row = emb + wid * EMBED_DIM;
    float x0 = row[lane];
    float x1 = row[lane + 32];
    float s = x0 * x0 + x1 * x1;
    #pragma unroll
    for (int o = 16; o > 0; o >>= 1) s += __shfl_xor_sync(0xFFFFFFFFu, s, o);
    float inv = 1.0f / sqrtf(s);
    g_enT[lane * NUM_EMBED + wid]        = x0 * inv;
    g_enT[(lane + 32) * NUM_EMBED + wid] = x1 * inv;
}

// ---------------------------------------------------------------------------
// Kernel 2: fused GEMM + argmax.
// CTA tile: 128 tokens x 128 codes, K=64 resident. 256 threads, 8x8 micro.
// Micro split {q*4, 64+q*4} for conflict-free LDS.128.
// ---------------------------------------------------------------------------
__global__ __launch_bounds__(256, 2)
void vq_argmax(const float* __restrict__ z, float* __restrict__ idx_out_f) {
    extern __shared__ float smem[];
    float* sA = smem;            // [64][128] tokens, k-major
    float* sB = smem + 64 * TM;  // [64][128] codes,  k-major

    const int tid = threadIdx.x;
    const int tx  = tid & 15;
    const int ty  = tid >> 4;
    const int m0  = blockIdx.x * TM;          // global token base (tile never crosses b)
    const int b   = m0 >> 12;
    const int hw0 = m0 & 4095;
    const float* zb = z + b * (EMBED_DIM * HW) + hw0;

    // Load token tile once: z[b][c][hw0 .. hw0+127] -> sA[c][m], coalesced float4
    #pragma unroll
    for (int i = 0; i < 8; i++) {
        int li = tid + i * 256;       // 0..2047 float4 slots
        int c  = li >> 5;
        int mv = (li & 31) << 2;
        float4 v = *(const float4*)(zb + c * HW + mv);
        *(float4*)(sA + c * TM + mv) = v;
    }

    float bv[8];
    int   bi[8];
    #pragma unroll
    for (int i = 0; i < 8; i++) { bv[i] = -3.0e38f; bi[i] = 0; }

    for (int nt = 0; nt < NUM_EMBED / TN; nt++) {
        const int n0 = nt * TN;
        __syncthreads();   // protect sB reuse (also covers sA on first iter)
        #pragma unroll
        for (int i = 0; i < 8; i++) {
            int li = tid + i * 256;
            int c  = li >> 5;
            int nv = (li & 31) << 2;
            float4 v = *(const float4*)(g_enT + c * NUM_EMBED + n0 + nv);
            *(float4*)(sB + c * TN + nv) = v;
        }
        __syncthreads();

        float acc[8][8];
        #pragma unroll
        for (int i = 0; i < 8; i++)
            #pragma unroll
            for (int j = 0; j < 8; j++) acc[i][j] = 0.0f;

        #pragma unroll 8
        for (int k = 0; k < 64; k++) {
            float a[8], bb2[8];
            *(float4*)(a)      = *(const float4*)(sA + k * TM + ty * 4);
            *(float4*)(a + 4)  = *(const float4*)(sA + k * TM + 64 + ty * 4);
            *(float4*)(bb2)    = *(const float4*)(sB + k * TN + tx * 4);
            *(float4*)(bb2 + 4)= *(const float4*)(sB + k * TN + 64 + tx * 4);
            #pragma unroll
            for (int i = 0; i < 8; i++)
                #pragma unroll
                for (int j = 0; j < 8; j++)
                    acc[i][j] += a[i] * bb2[j];
        }

        // running argmax (ascending code index within thread -> first-max on ties)
        #pragma unroll
        for (int i = 0; i < 8; i++) {
            #pragma unroll
            for (int j = 0; j < 8; j++) {
                int nloc = (j < 4) ? (tx * 4 + j) : (64 + tx * 4 + (j - 4));
                int idx  = n0 + nloc;
                float v  = acc[i][j];
                if (v > bv[i] || (v == bv[i] && idx < bi[i])) { bv[i] = v; bi[i] = idx; }
            }
        }
    }

    __syncthreads();
    // cross-thread reduction: overlay (val,idx) table on sB region: [128 rows][16 tx]
    float2* red = (float2*)sB;
    #pragma unroll
    for (int i = 0; i < 8; i++) {
        int mloc = (i < 4) ? (ty * 4 + i) : (64 + ty * 4 + (i - 4));
        red[mloc * 16 + tx] = make_float2(bv[i], __int_as_float(bi[i]));
    }
    __syncthreads();

    if (tid < TM) {
        float best = -3.0e38f;
        int besti  = 0x7FFFFFFF;
        #pragma unroll
        for (int x = 0; x < 16; x++) {
            float2 r = red[tid * 16 + x];
            int idx = __float_as_int(r.y);
            if (r.x > best || (r.x == best && idx < besti)) { best = r.x; besti = idx; }
        }
        int t = m0 + tid;
        g_idx[t] = besti;
        atomicAdd(&g_hist[besti], 1);
        idx_out_f[t] = (float)besti;
    }
}

// ---------------------------------------------------------------------------
// Kernel 3: gather z_q into out (b,c,h,w), accumulate per-block loss partials
// grid 2048 x 256, one float4 per thread (coalesced)
// ---------------------------------------------------------------------------
__global__ __launch_bounds__(256)
void vq_gather_loss(const float* __restrict__ z, const float* __restrict__ emb,
                    float* __restrict__ out) {
    int v = blockIdx.x * 256 + threadIdx.x;
    int e = v << 2;                 // element index in [B][C][H][W]
    int b = e >> 18;
    int c = (e >> 12) & 63;
    int hw = e & 4095;
    int t = (b << 12) | hw;

    float4 zv = *(const float4*)(z + e);
    int i0 = g_idx[t + 0];
    int i1 = g_idx[t + 1];
    int i2 = g_idx[t + 2];
    int i3 = g_idx[t + 3];
    float q0 = emb[i0 * EMBED_DIM + c];
    float q1 = emb[i1 * EMBED_DIM + c];
    float q2 = emb[i2 * EMBED_DIM + c];
    float q3 = emb[i3 * EMBED_DIM + c];
    float4 qv = make_float4(q0, q1, q2, q3);
    *(float4*)(out + e) = qv;

    float d0 = q0 - zv.x, d1 = q1 - zv.y, d2 = q2 - zv.z, d3 = q3 - zv.w;
    float s = d0 * d0 + d1 * d1 + d2 * d2 + d3 * d3;

    #pragma unroll
    for (int o = 16; o > 0; o >>= 1) s += __shfl_xor_sync(0xFFFFFFFFu, s, o);
    __shared__ float ws[8];
    int lane = threadIdx.x & 31, wid = threadIdx.x >> 5;
    if (lane == 0) ws[wid] = s;
    __syncthreads();
    if (threadIdx.x == 0) {
        float acc = 0.0f;
        #pragma unroll
        for (int i = 0; i < 8; i++) acc += ws[i];
        g_partial[blockIdx.x] = acc;
    }
}

// ---------------------------------------------------------------------------
// Kernel 4: finalize loss + perplexity (deterministic reductions)
// ---------------------------------------------------------------------------
__global__ __launch_bounds__(256)
void vq_finalize(float* __restrict__ out) {
    __shared__ float sh[256];
    int tid = threadIdx.x;

    float s = 0.0f;
    for (int i = tid; i < N_PART; i += 256) s += g_partial[i];
    sh[tid] = s;
    __syncthreads();
    for (int o = 128; o > 0; o >>= 1) {
        if (tid < o) sh[tid] += sh[tid + o];
        __syncthreads();
    }
    if (tid == 0) out[N_ELEM] = 1.25f * sh[0] / (float)N_ELEM;
    __syncthreads();

    float h = 0.0f;
    for (int i = tid; i < NUM_EMBED; i += 256) {
        float p = (float)g_hist[i] * (1.0f / (float)N_TOK);
        h += p * logf(p + 1e-10f);
    }
    sh[tid] = h;
    __syncthreads();
    for (int o = 128; o > 0; o >>= 1) {
        if (tid < o) sh[tid] += sh[tid + o];
        __syncthreads();
    }
    if (tid == 0) out[N_ELEM + 1] = expf(-sh[0]);
}

// ---------------------------------------------------------------------------
// Output layout (tuple order, all as float32):
//   [0, 2097152)           out  (b,c,h,w)
//   [2097152]              loss
//   [2097153]              perplexity
//   [2097154, 2097154+32768) idx_map
// ---------------------------------------------------------------------------
extern "C" void kernel_launch(void* const* d_in, const int* in_sizes, int n_in,
                              void* d_out, int out_size) {
    const float* z   = (const float*)d_in[0];
    const float* emb = (const float*)d_in[1];
    float* out = (float*)d_out;

    cudaFuncSetAttribute(vq_argmax, cudaFuncAttributeMaxDynamicSharedMemorySize,
                         64 * 1024);

    vq_zero_hist<<<(NUM_EMBED + 255) / 256, 256>>>();
    vq_normalize_embed<<<NUM_EMBED / 8, 256>>>(emb);
    vq_argmax<<<N_TOK / TM, 256, 64 * 1024>>>(z, out + N_ELEM + 2);
    vq_gather_loss<<<N_PART, 256>>>(z, emb, out);
    vq_finalize<<<1, 256>>>(out);
}

// round 4
// speedup vs baseline: 2.3088x; 2.3088x over previous
#include <cuda_runtime.h>
#include <cuda_fp16.h>
#include <math.h>
#include <stdint.h>

#define NUM_EMBED 8192
#define EMBED_DIM 64
#define BB 8
#define HH 64
#define WW 64
#define N_TOK   (BB*HH*WW)            /* 32768 */
#define N_ELEM  (BB*EMBED_DIM*HH*WW)  /* 2097152 */
#define HW      (HH*WW)               /* 4096 */
#define N_PART  2048

#define M_CTA   256                   /* tokens per CTA */
#define TN      128                   /* codes per tile */
#define N_TILES (NUM_EMBED / TN)      /* 64 */
#define NTHREADS 512                  /* 16 mma warps */

// SMEM (from 1024-aligned base):
//   A0 @ 0      : 256 rows x 128B  (fp16 term0, swizzled)
//   A1 @ 32768  : 256 rows x 128B  (fp16 term1)
//   B  @ 65536  : 2 bufs x [2 terms x 128 rows x 128B] = 2 x 32768
#define OFF_A1  32768
#define OFF_B   65536
#define SMEM_BYTES (131072 + 1024)

#define SWZ(o) ((o) ^ (((o) >> 3) & 0x70))

// ---------------------------------------------------------------------------
// device scratch (no allocation allowed)
// ---------------------------------------------------------------------------
__device__ __align__(16) __half g_e0[NUM_EMBED * EMBED_DIM];
__device__ __align__(16) __half g_e1[NUM_EMBED * EMBED_DIM];
__device__ int   g_idx[N_TOK];
__device__ int   g_hist[NUM_EMBED];
__device__ float g_partial[N_PART];

// ---------------------------------------------------------------------------
// asm helpers (all plain sm_80+ features; no 'a'-arch instructions)
// ---------------------------------------------------------------------------
__device__ __forceinline__ uint32_t smem_u32(const void* p) {
    uint32_t a;
    asm("{ .reg .u64 t; cvta.to.shared.u64 t, %1; cvt.u32.u64 %0, t; }" : "=r"(a) : "l"(p));
    return a;
}
#define LDSM_X4(r, addr)                                                         \
    asm volatile("ldmatrix.sync.aligned.m8n8.x4.shared.b16 {%0,%1,%2,%3}, [%4];" \
        : "=r"((r)[0]), "=r"((r)[1]), "=r"((r)[2]), "=r"((r)[3]) : "r"(addr))

#define MMA_16816(c, a, b0, b1)                                                  \
    asm volatile("mma.sync.aligned.m16n8k16.row.col.f32.f16.f16.f32 "            \
        "{%0,%1,%2,%3}, {%4,%5,%6,%7}, {%8,%9}, {%0,%1,%2,%3};"                  \
        : "+f"((c)[0]), "+f"((c)[1]), "+f"((c)[2]), "+f"((c)[3])                 \
        : "r"((a)[0]), "r"((a)[1]), "r"((a)[2]), "r"((a)[3]), "r"(b0), "r"(b1))

#define CP_ASYNC16(saddr, gptr)                                                  \
    asm volatile("cp.async.cg.shared.global [%0], [%1], 16;" :: "r"(saddr), "l"(gptr))
#define CP_COMMIT()  asm volatile("cp.async.commit_group;")
#define CP_WAIT1()   asm volatile("cp.async.wait_group 1;")
#define CP_WAIT0()   asm volatile("cp.async.wait_group 0;")

// ---------------------------------------------------------------------------
// Kernel 0: zero histogram
// ---------------------------------------------------------------------------
__global__ void vq_zero_hist() {
    int i = blockIdx.x * 256 + threadIdx.x;
    if (i < NUM_EMBED) g_hist[i] = 0;
}

// ---------------------------------------------------------------------------
// Kernel 1: normalize codebook rows + fp16x2 split, row-major [n][k]
// ---------------------------------------------------------------------------
__global__ void vq_prep_embed(const float* __restrict__ emb) {
    int wid  = (blockIdx.x * blockDim.x + threadIdx.x) >> 5;
    int lane = threadIdx.x & 31;
    if (wid >= NUM_EMBED) return;
    const float* row = emb + wid * EMBED_DIM;
    float x0 = row[lane];
    float x1 = row[lane + 32];
    float s = x0 * x0 + x1 * x1;
    #pragma unroll
    for (int o = 16; o > 0; o >>= 1) s += __shfl_xor_sync(0xFFFFFFFFu, s, o);
    float inv = 1.0f / sqrtf(s);
    #pragma unroll
    for (int h = 0; h < 2; h++) {
        int c = lane + h * 32;
        float xn = (h ? x1 : x0) * inv;
        __half h0 = __float2half(xn);
        __half h1 = __float2half(xn - __half2float(h0));
        g_e0[wid * EMBED_DIM + c] = h0;
        g_e1[wid * EMBED_DIM + c] = h1;
    }
}

// ---------------------------------------------------------------------------
// Kernel 2: fp16x2 split GEMM (mma.sync) + fused in-register argmax.
// 512 threads = 16 warps, layout 8(M) x 2(N). Warp tile 32 x 64.
// ---------------------------------------------------------------------------
__global__ __launch_bounds__(NTHREADS, 1)
void vq_argmax_mma(const float* __restrict__ z, float* __restrict__ idx_out_f) {
    extern __shared__ char dsm_raw[];
    const uint32_t raw   = smem_u32(dsm_raw);
    const uint32_t abase = (raw + 1023u) & ~1023u;

    const int tid    = threadIdx.x;
    const int wid    = tid >> 5;
    const int lane   = tid & 31;
    const int warp_m = wid & 7;        // 8 M-groups of 32 rows
    const int warp_n = wid >> 3;       // 2 N-groups of 64 cols
    const int wm0    = warp_m * 32;
    const int cn0    = warp_n * 64;
    const int grp    = lane >> 3;      // ldmatrix address group

    const int m0  = blockIdx.x * M_CTA;
    const int b   = m0 >> 12;
    const int hw0 = m0 & 4095;

    // --- async-load B tile t into buffer p ---
    auto load_b = [&](int t, int p) {
        const int n0 = t * TN;
        const uint32_t sb = abase + OFF_B + p * 32768;
        #pragma unroll
        for (int q = 0; q < 4; q++) {
            int i    = tid + q * NTHREADS;        // 0..2047
            int term = i >> 10;
            int rq   = i & 1023;
            int r    = rq >> 3;
            int ch   = rq & 7;
            const __half* src = term ? g_e1 : g_e0;
            const __half* gp  = src + (n0 + r) * EMBED_DIM + ch * 8;
            uint32_t sa = sb + term * 16384 + SWZ(r * 128 + ch * 16);
            CP_ASYNC16(sa, gp);
        }
    };

    // kick off tile 0 loads first
    load_b(0, 0);
    CP_COMMIT();

    // --- prologue: load z tile, split fp16x2 into swizzled A0/A1 ---
    {
        const float* zb = z + b * (EMBED_DIM * HW) + hw0;
        char* sm = dsm_raw + (abase - raw);
        for (int i = tid; i < (M_CTA * EMBED_DIM) / 4; i += NTHREADS) {
            int c  = i >> 6;               // channel = K index
            int m4 = (i & 63) << 2;        // token row base
            float4 v = *(const float4*)(zb + c * HW + m4);
            float xs[4] = {v.x, v.y, v.z, v.w};
            #pragma unroll
            for (int e = 0; e < 4; e++) {
                float x = xs[e];
                __half h0 = __float2half(x);
                __half h1 = __float2half(x - __half2float(h0));
                int off = SWZ((m4 + e) * 128 + c * 2);
                *(__half*)(sm + off)          = h0;
                *(__half*)(sm + OFF_A1 + off) = h1;
            }
        }
    }
    __syncthreads();

    float bv[4];
    int   bi[4];
    #pragma unroll
    for (int s = 0; s < 4; s++) { bv[s] = -3.0e38f; bi[s] = 0x7FFFFFFF; }

    // precompute ldmatrix lane offsets
    const int a_row  = wm0 + (grp & 1) * 8 + (lane & 7);
    const int b_rowL = cn0 + (grp & 1) * 8 + (lane & 7);
    const int k_off  = (grp >> 1) * 8;

    for (int t = 0; t < N_TILES; t++) {
        const int p  = t & 1;
        const int n0 = t * TN;

        if (t + 1 < N_TILES) {
            load_b(t + 1, (t + 1) & 1);
            CP_COMMIT();
            CP_WAIT1();         // tile t's group complete
        } else {
            CP_WAIT0();
        }
        __syncthreads();

        float acc[2][8][4];
        #pragma unroll
        for (int i = 0; i < 2; i++)
            #pragma unroll
            for (int j = 0; j < 8; j++)
                #pragma unroll
                for (int q = 0; q < 4; q++) acc[i][j][q] = 0.0f;

        const uint32_t bbuf = abase + OFF_B + p * 32768;
        #pragma unroll
        for (int ks = 0; ks < 4; ks++) {
            const int kb = ks * 16 + k_off;
            uint32_t a0f[2][4], a1f[2][4];
            #pragma unroll
            for (int i = 0; i < 2; i++) {
                uint32_t ao = abase + SWZ((a_row + i * 16) * 128 + kb * 2);
                LDSM_X4(a0f[i], ao);
                LDSM_X4(a1f[i], ao + OFF_A1);
            }
            #pragma unroll
            for (int j2 = 0; j2 < 4; j2++) {
                uint32_t bo = bbuf + SWZ((b_rowL + j2 * 16) * 128 + kb * 2);
                uint32_t b0r[4], b1r[4];
                LDSM_X4(b0r, bo);
                LDSM_X4(b1r, bo + 16384);
                #pragma unroll
                for (int sub = 0; sub < 2; sub++) {
                    const int j = j2 * 2 + sub;
                    #pragma unroll
                    for (int i = 0; i < 2; i++) {
                        MMA_16816(acc[i][j], a0f[i], b0r[sub], b0r[2 + sub]);
                        MMA_16816(acc[i][j], a0f[i], b1r[sub], b1r[2 + sub]);
                        MMA_16816(acc[i][j], a1f[i], b0r[sub], b0r[2 + sub]);
                    }
                }
            }
        }

        // fused argmax on accumulators (ascending index; strict > keeps first)
        #pragma unroll
        for (int i = 0; i < 2; i++) {
            #pragma unroll
            for (int j = 0; j < 8; j++) {
                int cbase = n0 + cn0 + j * 8 + (lane & 3) * 2;
                #pragma unroll
                for (int h = 0; h < 2; h++) {
                    int s = i * 2 + h;
                    float v0 = acc[i][j][2 * h + 0];
                    float v1 = acc[i][j][2 * h + 1];
                    if (v0 > bv[s]) { bv[s] = v0; bi[s] = cbase; }
                    if (v1 > bv[s]) { bv[s] = v1; bi[s] = cbase + 1; }
                }
            }
        }
        __syncthreads();   // all warps done with buf p before it is refilled
    }

    // --- quad reduce (cols live across lane&3) ---
    #pragma unroll
    for (int s = 0; s < 4; s++) {
        #pragma unroll
        for (int off = 1; off < 4; off <<= 1) {
            float ov = __shfl_xor_sync(0xFFFFFFFFu, bv[s], off);
            int   oi = __shfl_xor_sync(0xFFFFFFFFu, bi[s], off);
            if (ov > bv[s] || (ov == bv[s] && oi < bi[s])) { bv[s] = ov; bi[s] = oi; }
        }
    }

    // --- merge the two N warp-groups via smem table [256 rows][2] ---
    float2* table = (float2*)(dsm_raw + (abase - raw) + OFF_B);
    if ((lane & 3) == 0) {
        #pragma unroll
        for (int s = 0; s < 4; s++) {
            int row = wm0 + (s >> 1) * 16 + (s & 1) * 8 + (lane >> 2);
            table[row * 2 + warp_n] = make_float2(bv[s], __int_as_float(bi[s]));
        }
    }
    __syncthreads();

    if (tid < M_CTA) {
        float2 r0 = table[tid * 2 + 0];
        float2 r1 = table[tid * 2 + 1];
        float best = r0.x;
        int besti  = __float_as_int(r0.y);
        int i1     = __float_as_int(r1.y);
        if (r1.x > best || (r1.x == best && i1 < besti)) { best = r1.x; besti = i1; }
        int token = m0 + tid;
        g_idx[token] = besti;
        atomicAdd(&g_hist[besti], 1);
        idx_out_f[token] = (float)besti;
    }
}

// ---------------------------------------------------------------------------
// Kernel 3: gather z_q into out (b,c,h,w), per-block loss partials
// ---------------------------------------------------------------------------
__global__ __launch_bounds__(256)
void vq_gather_loss(const float* __restrict__ z, const float* __restrict__ emb,
                    float* __restrict__ out) {
    int v = blockIdx.x * 256 + threadIdx.x;
    int e = v << 2;
    int c = (e >> 12) & 63;
    int t = ((e >> 18) << 12) | (e & 4095);

    float4 zv = *(const float4*)(z + e);
    int i0 = g_idx[t + 0];
    int i1 = g_idx[t + 1];
    int i2 = g_idx[t + 2];
    int i3 = g_idx[t + 3];
    float q0 = emb[i0 * EMBED_DIM + c];
    float q1 = emb[i1 * EMBED_DIM + c];
    float q2 = emb[i2 * EMBED_DIM + c];
    float q3 = emb[i3 * EMBED_DIM + c];
    *(float4*)(out + e) = make_float4(q0, q1, q2, q3);

    float d0 = q0 - zv.x, d1 = q1 - zv.y, d2 = q2 - zv.z, d3 = q3 - zv.w;
    float s = d0 * d0 + d1 * d1 + d2 * d2 + d3 * d3;

    #pragma unroll
    for (int o = 16; o > 0; o >>= 1) s += __shfl_xor_sync(0xFFFFFFFFu, s, o);
    __shared__ float ws[8];
    int lane = threadIdx.x & 31, wrp = threadIdx.x >> 5;
    if (lane == 0) ws[wrp] = s;
    __syncthreads();
    if (threadIdx.x == 0) {
        float acc = 0.0f;
        #pragma unroll
        for (int i = 0; i < 8; i++) acc += ws[i];
        g_partial[blockIdx.x] = acc;
    }
}

// ---------------------------------------------------------------------------
// Kernel 4: finalize loss + perplexity
// ---------------------------------------------------------------------------
__global__ __launch_bounds__(256)
void vq_finalize(float* __restrict__ out) {
    __shared__ float sh[256];
    int tid = threadIdx.x;

    float s = 0.0f;
    for (int i = tid; i < N_PART; i += 256) s += g_partial[i];
    sh[tid] = s;
    __syncthreads();
    for (int o = 128; o > 0; o >>= 1) {
        if (tid < o) sh[tid] += sh[tid + o];
        __syncthreads();
    }
    if (tid == 0) out[N_ELEM] = 1.25f * sh[0] / (float)N_ELEM;
    __syncthreads();

    float h = 0.0f;
    for (int i = tid; i < NUM_EMBED; i += 256) {
        float p = (float)g_hist[i] * (1.0f / (float)N_TOK);
        h += p * logf(p + 1e-10f);
    }
    sh[tid] = h;
    __syncthreads();
    for (int o = 128; o > 0; o >>= 1) {
        if (tid < o) sh[tid] += sh[tid + o];
        __syncthreads();
    }
    if (tid == 0) out[N_ELEM + 1] = expf(-sh[0]);
}

// ---------------------------------------------------------------------------
// Output layout (all float32): [0, N_ELEM) out | loss | perplexity | idx_map
// ---------------------------------------------------------------------------
extern "C" void kernel_launch(void* const* d_in, const int* in_sizes, int n_in,
                              void* d_out, int out_size) {
    const float* z   = (const float*)d_in[0];
    const float* emb = (const float*)d_in[1];
    float* out = (float*)d_out;

    cudaFuncSetAttribute(vq_argmax_mma, cudaFuncAttributeMaxDynamicSharedMemorySize,
                         SMEM_BYTES);

    vq_zero_hist<<<(NUM_EMBED + 255) / 256, 256>>>();
    vq_prep_embed<<<NUM_EMBED / 8, 256>>>(emb);
    vq_argmax_mma<<<N_TOK / M_CTA, NTHREADS, SMEM_BYTES>>>(z, out + N_ELEM + 2);
    vq_gather_loss<<<N_PART, 256>>>(z, emb, out);
    vq_finalize<<<1, 256>>>(out);
}